// round 9
// baseline (speedup 1.0000x reference)
#include <cuda_runtime.h>
#include <cuda_bf16.h>
#include <cstdint>

#define BB   8
#define SS   4096
#define DD   1024
#define KK   128
#define MM   (BB * SS)
#define LN_EPS 1e-5f

// ---------------- scratch (static device arrays; no allocations) ----------------
__device__ float g_beta [ (size_t)MM * KK ];   // (B,S,K)   16 MB
__device__ float g_srseq[ (size_t)MM * KK ];   // (S,B,K) tf32-rounded, 16 MB
__device__ float g_y    [ (size_t)MM * DD ];   // (S*B, D) 128 MB
__device__ float g_win_tf [ (size_t)KK * DD ]; // W_in  tf32-rounded
__device__ float g_wout_tf[ (size_t)DD * KK ]; // W_out tf32-rounded

// ============================ helpers ============================
__device__ __forceinline__ uint32_t smem_u32(const void* p) {
    uint32_t a;
    asm("{ .reg .u64 t; cvta.to.shared.u64 t, %1; cvt.u32.u64 %0, t; }" : "=r"(a) : "l"(p));
    return a;
}
__device__ __forceinline__ uint32_t f2tf(float f) {
    uint32_t u;
    asm("cvt.rna.tf32.f32 %0, %1;" : "=r"(u) : "f"(f));
    return u;
}
__device__ __forceinline__ void cp16(void* dst, const void* src) {
    uint32_t d = smem_u32(dst);
    asm volatile("cp.async.cg.shared.global [%0], [%1], 16;" :: "r"(d), "l"(src));
}
#define CP_COMMIT() asm volatile("cp.async.commit_group;" ::: "memory")
#define CP_WAIT1()  asm volatile("cp.async.wait_group 1;"  ::: "memory")

#define MMA_TF32(c, a, b) \
    asm volatile("mma.sync.aligned.m16n8k8.row.col.f32.tf32.tf32.f32 " \
        "{%0,%1,%2,%3}, {%4,%5,%6,%7}, {%8,%9}, {%0,%1,%2,%3};" \
        : "+f"((c)[0]), "+f"((c)[1]), "+f"((c)[2]), "+f"((c)[3]) \
        : "r"((a)[0]), "r"((a)[1]), "r"((a)[2]), "r"((a)[3]), \
          "r"((b)[0]), "r"((b)[1]))

// ============================================================================
// tf32 tensor-core GEMM:  C[bm:+64, bn:+128] = A[64, KD] * Bt[128, KD]^T (+bias)
// 128 threads = 4 warps; each warp owns 64x32 (cols wn*32). K chunks of 32;
// 2-stage cp.async double buffer; 55.3 KB smem -> 4 CTAs/SM for gap-filling.
// Operands pre-rounded tf32 bits: inner loop = pure LDS + MMA.
// ============================================================================
#define KC   32
#define SPAD 36
#define ASTG_F (64 * SPAD)      // A tile floats per stage
#define BSTG_F (128 * SPAD)     // B tile floats per stage
#define NSTG 2

template<int KD>
__global__ __launch_bounds__(128, 4)
void gemm_mma(const float* __restrict__ A, const float* __restrict__ Bt,
              float* __restrict__ C, const float* __restrict__ bias, int ldc)
{
    constexpr int NCH = KD / KC;
    extern __shared__ float sm[];
    float* AsB = sm;                          // [NSTG][64][SPAD]
    float* BsB = sm + NSTG * ASTG_F;          // [NSTG][128][SPAD]

    const int tid = threadIdx.x;
    const int bn = blockIdx.x * 128;
    const int bm = blockIdx.y * 64;
    const int lane = tid & 31;
    const int wn = tid >> 5;     // 0..3

    float acc[4][4][4];
    #pragma unroll
    for (int i = 0; i < 4; i++)
        #pragma unroll
        for (int j = 0; j < 4; j++)
            #pragma unroll
            for (int r = 0; r < 4; r++) acc[i][j][r] = 0.0f;

    const float* Ag = A + (size_t)bm * KD;
    const float* Bg = Bt + (size_t)bn * KD;

    // A: 64 rows x 8 f4 = 512; B: 128 x 8 = 1024; 128 threads
    auto prefetch = [&](int ch, int st) {
        float* as = AsB + st * ASTG_F;
        float* bs = BsB + st * BSTG_F;
        #pragma unroll
        for (int it = 0; it < 4; it++) {
            int idx = tid + it * 128;
            int r = idx >> 3, c4 = idx & 7;
            cp16(as + r * SPAD + c4 * 4, Ag + (size_t)r * KD + ch * KC + c4 * 4);
        }
        #pragma unroll
        for (int it = 0; it < 8; it++) {
            int idx = tid + it * 128;
            int r = idx >> 3, c4 = idx & 7;
            cp16(bs + r * SPAD + c4 * 4, Bg + (size_t)r * KD + ch * KC + c4 * 4);
        }
    };

    auto compute = [&](int st) {
        const uint32_t* as = (const uint32_t*)(AsB + st * ASTG_F)
                           + (lane >> 2) * SPAD + (lane & 3);
        const uint32_t* bs = (const uint32_t*)(BsB + st * BSTG_F)
                           + (wn * 32 + (lane >> 2)) * SPAD + (lane & 3);
        uint32_t a[2][4][4], b[2][4][2];

        auto load_frag = [&](int buf, int ks) {
            const int k = ks * 8;
            #pragma unroll
            for (int mt = 0; mt < 4; mt++) {
                const uint32_t* p = as + mt * 16 * SPAD + k;
                a[buf][mt][0] = p[0];
                a[buf][mt][1] = p[8 * SPAD];
                a[buf][mt][2] = p[4];
                a[buf][mt][3] = p[8 * SPAD + 4];
            }
            #pragma unroll
            for (int nt = 0; nt < 4; nt++) {
                const uint32_t* p = bs + nt * 8 * SPAD + k;
                b[buf][nt][0] = p[0];
                b[buf][nt][1] = p[4];
            }
        };

        load_frag(0, 0);
        #pragma unroll
        for (int ks = 0; ks < KC / 8; ks++) {
            const int cur = ks & 1;
            if (ks + 1 < KC / 8) load_frag(cur ^ 1, ks + 1);
            #pragma unroll
            for (int mt = 0; mt < 4; mt++)
                #pragma unroll
                for (int nt = 0; nt < 4; nt++)
                    MMA_TF32(acc[mt][nt], a[cur][mt], b[cur][nt]);
        }
    };

    // prologue: preload chunks 0 and 1
    prefetch(0, 0); CP_COMMIT();
    if (NCH > 1) prefetch(1, 1);
    CP_COMMIT();

    for (int ch = 0; ch < NCH; ch++) {
        CP_WAIT1();
        __syncthreads();
        compute(ch & 1);
        __syncthreads();
        if (ch + 2 < NCH) prefetch(ch + 2, ch & 1);
        CP_COMMIT();
    }

    // ---- epilogue ----
    #pragma unroll
    for (int nt = 0; nt < 4; nt++) {
        const int col = bn + wn * 32 + nt * 8 + 2 * (lane & 3);
        float2 bv;
        if (bias) bv = *(const float2*)(bias + col);
        else      bv = make_float2(0.0f, 0.0f);
        #pragma unroll
        for (int mt = 0; mt < 4; mt++) {
            const int row = bm + mt * 16 + (lane >> 2);
            float2 v0 = { acc[mt][nt][0] + bv.x, acc[mt][nt][1] + bv.y };
            float2 v1 = { acc[mt][nt][2] + bv.x, acc[mt][nt][3] + bv.y };
            *(float2*)(C + (size_t)row * ldc + col) = v0;
            *(float2*)(C + (size_t)(row + 8) * ldc + col) = v1;
        }
    }
}

// ============================================================================
// tf32 pre-round: dst[i] = round_tf32(src[i])
// ============================================================================
__global__ __launch_bounds__(256)
void tf32_round(const float* __restrict__ src, float* __restrict__ dst, int n)
{
    int i = blockIdx.x * blockDim.x + threadIdx.x;
    if (i < n) dst[i] = __uint_as_float(f2tf(src[i]));
}

// ============================================================================
// Scan. Per-mode decay mag*|R_kk| (R diagonal). If all decays <= 0.5,
// chunk the sequence (CH=32) with a 32-step warmup (error <= 0.5^32).
// Batched loads (8 independent LDGs in flight). Runtime guards keep this
// exact: scan_par no-ops unless (diag && decay ok); scan_serial covers rest.
// sr_seq stored tf32-rounded (== rounding at GEMM2 load); srf/sif full fp32.
// ============================================================================
#define SCAN_CH   32
#define SCAN_NCH  (SS / SCAN_CH)
#define SCAN_WARM 32

__device__ __forceinline__ bool r_is_diag(const float* R, int k) {
    bool ok = true;
    for (int i = k; i < KK * KK; i += KK) {
        int r = i / KK, c = i - r * KK;
        if (r != c && R[i] != 0.0f) ok = false;
    }
    return ok;
}

__global__ __launch_bounds__(KK)
void scan_par(const float* __restrict__ alpha, const float* __restrict__ omega,
              const float* __restrict__ R,
              float* __restrict__ srf, float* __restrict__ sif)
{
    const int chunk = blockIdx.x, b = blockIdx.y, k = threadIdx.x;

    const bool diag = (__syncthreads_and(r_is_diag(R, k) ? 1 : 0) != 0);
    const float mag = 1.0f / (1.0f + expf(-alpha[k]));
    const float dk = R[k * KK + k];
    const bool dec_ok = (__syncthreads_and((mag * fabsf(dk)) <= 0.5f ? 1 : 0) != 0);
    if (!(diag && dec_ok)) return;

    const float cth = cosf(omega[k]);
    const float sth = sinf(omega[k]);
    const float Ac = dk * mag * cth;
    const float Bc = dk * mag * sth;

    const int t0 = chunk * SCAN_CH;
    float sr = 0.0f, si = 0.0f;

    // ---- warmup: 32 steps in 4 batches of 8 ----
    if (chunk > 0) {
        const float* wp = g_beta + ((size_t)b * SS + t0 - SCAN_WARM) * KK + k;
        #pragma unroll
        for (int g = 0; g < SCAN_WARM / 8; g++) {
            float buf[8];
            #pragma unroll
            for (int i = 0; i < 8; i++)
                buf[i] = __ldg(wp + (size_t)(g * 8 + i) * KK);
            #pragma unroll
            for (int i = 0; i < 8; i++) {
                float gb = dk * buf[i];
                float nr = fmaf(Ac, sr, fmaf(-Bc, si, gb));
                float ni = fmaf(Bc, sr, Ac * si);
                sr = nr; si = ni;
            }
        }
    }

    // ---- main: 32 steps in 4 batches of 8 ----
    const float* mp = g_beta + ((size_t)b * SS + t0) * KK + k;
    float* sp = g_srseq + ((size_t)t0 * BB + b) * KK + k;
    #pragma unroll
    for (int g = 0; g < SCAN_CH / 8; g++) {
        float buf[8];
        #pragma unroll
        for (int i = 0; i < 8; i++)
            buf[i] = __ldg(mp + (size_t)(g * 8 + i) * KK);
        #pragma unroll
        for (int i = 0; i < 8; i++) {
            float gb = dk * buf[i];
            float nr = fmaf(Ac, sr, fmaf(-Bc, si, gb));
            float ni = fmaf(Bc, sr, Ac * si);
            sr = nr; si = ni;
            sp[(size_t)(g * 8 + i) * (BB * KK)] = __uint_as_float(f2tf(sr));
        }
    }

    if (chunk == SCAN_NCH - 1) { srf[b * KK + k] = sr; sif[b * KK + k] = si; }
}

__global__ __launch_bounds__(KK)
void scan_serial(const float* __restrict__ alpha, const float* __restrict__ omega,
                 const float* __restrict__ R,
                 float* __restrict__ srf, float* __restrict__ sif)
{
    const int b = blockIdx.x, k = threadIdx.x;

    const bool diag = (__syncthreads_and(r_is_diag(R, k) ? 1 : 0) != 0);
    const float mag = 1.0f / (1.0f + expf(-alpha[k]));
    const float dk = R[k * KK + k];
    const bool dec_ok = (__syncthreads_and((mag * fabsf(dk)) <= 0.5f ? 1 : 0) != 0);
    if (diag && dec_ok) return;   // parallel kernel handled it

    const float cth = cosf(omega[k]);
    const float sth = sinf(omega[k]);

    const float* bp = g_beta + ((size_t)b * SS) * KK + k;
    float* sp = g_srseq + (size_t)b * KK + k;
    float sr = 0.0f, si = 0.0f;

    if (diag) {
        const float Ac = dk * mag * cth;
        const float Bc = dk * mag * sth;
        #pragma unroll 4
        for (int t = 0; t < SS; t++) {
            float gb = dk * __ldg(bp + (size_t)t * KK);
            float nr = fmaf(Ac, sr, fmaf(-Bc, si, gb));
            float ni = fmaf(Bc, sr, Ac * si);
            sr = nr; si = ni;
            sp[(size_t)t * (BB * KK)] = __uint_as_float(f2tf(sr));
        }
    } else {
        __shared__ float nrs[KK], nis[KK];
        for (int t = 0; t < SS; t++) {
            float bt = __ldg(bp + (size_t)t * KK);
            float nr = fmaf(mag * cth, sr, fmaf(-mag * sth, si, bt));
            float ni = mag * fmaf(sr, sth, si * cth);
            nrs[k] = nr; nis[k] = ni;
            __syncthreads();
            float a0 = 0.0f, a1 = 0.0f;
            #pragma unroll 8
            for (int j = 0; j < KK; j++) {
                float rj = R[j * KK + k];
                a0 = fmaf(nrs[j], rj, a0);
                a1 = fmaf(nis[j], rj, a1);
            }
            __syncthreads();
            sr = a0; si = a1;
            sp[(size_t)t * (BB * KK)] = __uint_as_float(f2tf(sr));
        }
    }
    srf[b * KK + k] = sr;
    sif[b * KK + k] = si;
}

// ============================================================================
// LayerNorm + transpose, warp-per-row: row r = s*B + b of g_y -> out[b][s][:]
// ============================================================================
__global__ __launch_bounds__(256)
void ln_kernel(const float* __restrict__ g, const float* __restrict__ bb,
               float* __restrict__ out)
{
    const int r = blockIdx.x * 8 + (threadIdx.x >> 5);
    const int lane = threadIdx.x & 31;

    const float4* yp = (const float4*)(g_y + (size_t)r * DD);

    float4 v[8];
    #pragma unroll
    for (int i = 0; i < 8; i++) v[i] = yp[lane + i * 32];

    float sum = 0.0f, sq = 0.0f;
    #pragma unroll
    for (int i = 0; i < 8; i++) {
        sum += (v[i].x + v[i].y) + (v[i].z + v[i].w);
        sq = fmaf(v[i].x, v[i].x, sq);
        sq = fmaf(v[i].y, v[i].y, sq);
        sq = fmaf(v[i].z, v[i].z, sq);
        sq = fmaf(v[i].w, v[i].w, sq);
    }
    #pragma unroll
    for (int o = 16; o > 0; o >>= 1) {
        sum += __shfl_xor_sync(0xffffffffu, sum, o);
        sq  += __shfl_xor_sync(0xffffffffu, sq,  o);
    }

    const float mu  = sum * (1.0f / DD);
    const float var = sq * (1.0f / DD) - mu * mu;
    const float inv = rsqrtf(var + LN_EPS);

    const int s = r >> 3;            // r = s*B + b, B=8
    const int b = r & 7;
    float4* op = (float4*)(out + ((size_t)b * SS + s) * DD);

    #pragma unroll
    for (int i = 0; i < 8; i++) {
        const float4 gg = ((const float4*)g)[lane + i * 32];
        const float4 b4 = ((const float4*)bb)[lane + i * 32];
        float4 o;
        o.x = fmaf((v[i].x - mu) * inv, gg.x, b4.x);
        o.y = fmaf((v[i].y - mu) * inv, gg.y, b4.y);
        o.z = fmaf((v[i].z - mu) * inv, gg.z, b4.z);
        o.w = fmaf((v[i].w - mu) * inv, gg.w, b4.w);
        op[lane + i * 32] = o;
    }
}

// ============================================================================
// launch
// ============================================================================
extern "C" void kernel_launch(void* const* d_in, const int* in_sizes, int n_in,
                              void* d_out, int out_size)
{
    const float* x     = (const float*)d_in[0];  // (B,S,D)
    const float* alpha = (const float*)d_in[1];  // (K)
    const float* omega = (const float*)d_in[2];  // (K)
    const float* W_in  = (const float*)d_in[3];  // (K,D)
    const float* R     = (const float*)d_in[4];  // (K,K)
    const float* W_out = (const float*)d_in[5];  // (D,K)
    const float* b_out = (const float*)d_in[6];  // (D)
    const float* ln_g  = (const float*)d_in[7];  // (D)
    const float* ln_b  = (const float*)d_in[8];  // (D)

    float* out = (float*)d_out;                   // (B,S,D)
    float* srf = out + (size_t)BB * SS * DD;      // (B,K)
    float* sif = srf + (size_t)BB * KK;           // (B,K)

    float* beta_p;  cudaGetSymbolAddress((void**)&beta_p,  g_beta);
    float* srseq_p; cudaGetSymbolAddress((void**)&srseq_p, g_srseq);
    float* y_p;     cudaGetSymbolAddress((void**)&y_p,     g_y);
    float* win_p;   cudaGetSymbolAddress((void**)&win_p,   g_win_tf);
    float* wout_p;  cudaGetSymbolAddress((void**)&wout_p,  g_wout_tf);

    const int SMEM = NSTG * (ASTG_F + BSTG_F) * (int)sizeof(float);   // 55296 B
    cudaFuncSetAttribute(gemm_mma<1024>,
                         cudaFuncAttributeMaxDynamicSharedMemorySize, SMEM);
    cudaFuncSetAttribute(gemm_mma<128>,
                         cudaFuncAttributeMaxDynamicSharedMemorySize, SMEM);
    cudaFuncSetAttribute(gemm_mma<1024>,
                         cudaFuncAttributePreferredSharedMemoryCarveout, 100);
    cudaFuncSetAttribute(gemm_mma<128>,
                         cudaFuncAttributePreferredSharedMemoryCarveout, 100);

    // 0) pre-round weights to tf32 (tiny)
    tf32_round<<<(KK * DD + 255) / 256, 256>>>(W_in, win_p, KK * DD);
    tf32_round<<<(DD * KK + 255) / 256, 256>>>(W_out, wout_p, DD * KK);

    // 1) beta = x @ W_in^T  (x raw bits -> tf32 truncation; W_in rounded)
    gemm_mma<1024><<<dim3(1, MM / 64), 128, SMEM>>>(x, win_p, beta_p, nullptr, KK);

    // 2) scan (parallel fast path + exact fallback; exactly one does work)
    scan_par<<<dim3(SCAN_NCH, BB), KK>>>(alpha, omega, R, srf, sif);
    scan_serial<<<BB, KK>>>(alpha, omega, R, srf, sif);

    // 3) y = sr_seq @ W_out^T + b_out  (both pre-rounded tf32)
    gemm_mma<128><<<dim3(DD / 128, MM / 64), 128, SMEM>>>(srseq_p, wout_p, y_p, b_out, DD);

    // 4) LayerNorm + transpose to (B,S,D)
    ln_kernel<<<MM / 8, 256>>>(ln_g, ln_b, out);
}

// round 10
// speedup vs baseline: 1.0721x; 1.0721x over previous
#include <cuda_runtime.h>
#include <cuda_fp16.h>
#include <cstdint>

#define BB   8
#define SS   4096
#define DD   1024
#define KK   128
#define MM   (BB * SS)
#define LN_EPS 1e-5f

// ---------------- scratch (static device arrays; no allocations) ----------------
__device__ float  g_beta   [ (size_t)MM * KK ];  // beta TRANSPOSED: (B,K,S) 16 MB
__device__ __half g_srseq_h[ (size_t)MM * KK ];  // (S,B,K) fp16, 8 MB
__device__ float  g_y      [ (size_t)MM * DD ];  // (S*B, D) 128 MB
__device__ float  g_win_tf [ (size_t)KK * DD ];  // W_in  tf32-rounded
__device__ __half g_wout_h [ (size_t)DD * KK ];  // W_out fp16

// ============================ helpers ============================
__device__ __forceinline__ uint32_t smem_u32(const void* p) {
    uint32_t a;
    asm("{ .reg .u64 t; cvta.to.shared.u64 t, %1; cvt.u32.u64 %0, t; }" : "=r"(a) : "l"(p));
    return a;
}
__device__ __forceinline__ uint32_t f2tf(float f) {
    uint32_t u;
    asm("cvt.rna.tf32.f32 %0, %1;" : "=r"(u) : "f"(f));
    return u;
}
__device__ __forceinline__ void cp16(void* dst, const void* src) {
    uint32_t d = smem_u32(dst);
    asm volatile("cp.async.cg.shared.global [%0], [%1], 16;" :: "r"(d), "l"(src));
}
#define CP_COMMIT() asm volatile("cp.async.commit_group;" ::: "memory")
#define CP_WAIT1()  asm volatile("cp.async.wait_group 1;"  ::: "memory")

#define MMA_TF32(c, a, b) \
    asm volatile("mma.sync.aligned.m16n8k8.row.col.f32.tf32.tf32.f32 " \
        "{%0,%1,%2,%3}, {%4,%5,%6,%7}, {%8,%9}, {%0,%1,%2,%3};" \
        : "+f"((c)[0]), "+f"((c)[1]), "+f"((c)[2]), "+f"((c)[3]) \
        : "r"((a)[0]), "r"((a)[1]), "r"((a)[2]), "r"((a)[3]), \
          "r"((b)[0]), "r"((b)[1]))

#define MMA_F16(c, a, b) \
    asm volatile("mma.sync.aligned.m16n8k16.row.col.f32.f16.f16.f32 " \
        "{%0,%1,%2,%3}, {%4,%5,%6,%7}, {%8,%9}, {%0,%1,%2,%3};" \
        : "+f"((c)[0]), "+f"((c)[1]), "+f"((c)[2]), "+f"((c)[3]) \
        : "r"((a)[0]), "r"((a)[1]), "r"((a)[2]), "r"((a)[3]), \
          "r"((b)[0]), "r"((b)[1]))

// ============================================================================
// GEMM1 (tf32): beta^T = (x @ W_in^T)^T, written as beta_t (B,K,S).
// 256 threads = 8 warps; warp (wm,wn) owns 64x32; K chunks of 32; NSTG=2.
// Operands: x raw fp32 bits (tf32 truncation), W_in pre-rounded.
// ============================================================================
#define KC   32
#define SPAD 36
#define STG_F (128 * SPAD)
#define NSTG 2

__global__ __launch_bounds__(256, 2)
void gemm_beta(const float* __restrict__ A, const float* __restrict__ Bt)
{
    constexpr int KD = 1024;
    constexpr int NCH = KD / KC;
    extern __shared__ float sm[];
    float* AsB = sm;
    float* BsB = sm + NSTG * STG_F;

    const int tid = threadIdx.x;
    const int bm = blockIdx.y * 128;          // bn = 0 (N = 128)
    const int lane = tid & 31;
    const int w = tid >> 5;
    const int wm = w >> 2;
    const int wn = w & 3;

    float acc[4][4][4];
    #pragma unroll
    for (int i = 0; i < 4; i++)
        #pragma unroll
        for (int j = 0; j < 4; j++)
            #pragma unroll
            for (int r = 0; r < 4; r++) acc[i][j][r] = 0.0f;

    const float* Ag = A + (size_t)bm * KD;
    const float* Bg = Bt;

    auto prefetch = [&](int ch, int st) {
        float* as = AsB + st * STG_F;
        float* bs = BsB + st * STG_F;
        #pragma unroll
        for (int it = 0; it < 4; it++) {
            int idx = tid + it * 256;
            int r = idx >> 3, c4 = idx & 7;
            cp16(as + r * SPAD + c4 * 4, Ag + (size_t)r * KD + ch * KC + c4 * 4);
            cp16(bs + r * SPAD + c4 * 4, Bg + (size_t)r * KD + ch * KC + c4 * 4);
        }
    };

    auto compute = [&](int st) {
        const uint32_t* as = (const uint32_t*)(AsB + st * STG_F)
                           + (wm * 64 + (lane >> 2)) * SPAD + (lane & 3);
        const uint32_t* bs = (const uint32_t*)(BsB + st * STG_F)
                           + (wn * 32 + (lane >> 2)) * SPAD + (lane & 3);
        uint32_t a[2][4][4], b[2][4][2];
        auto load_frag = [&](int buf, int ks) {
            const int k = ks * 8;
            #pragma unroll
            for (int mt = 0; mt < 4; mt++) {
                const uint32_t* p = as + mt * 16 * SPAD + k;
                a[buf][mt][0] = p[0];
                a[buf][mt][1] = p[8 * SPAD];
                a[buf][mt][2] = p[4];
                a[buf][mt][3] = p[8 * SPAD + 4];
            }
            #pragma unroll
            for (int nt = 0; nt < 4; nt++) {
                const uint32_t* p = bs + nt * 8 * SPAD + k;
                b[buf][nt][0] = p[0];
                b[buf][nt][1] = p[4];
            }
        };
        load_frag(0, 0);
        #pragma unroll
        for (int ks = 0; ks < KC / 8; ks++) {
            const int cur = ks & 1;
            if (ks + 1 < KC / 8) load_frag(cur ^ 1, ks + 1);
            #pragma unroll
            for (int mt = 0; mt < 4; mt++)
                #pragma unroll
                for (int nt = 0; nt < 4; nt++)
                    MMA_TF32(acc[mt][nt], a[cur][mt], b[cur][nt]);
        }
    };

    prefetch(0, 0); CP_COMMIT();
    prefetch(1, 1); CP_COMMIT();
    for (int ch = 0; ch < NCH; ch++) {
        CP_WAIT1();
        __syncthreads();
        compute(ch & 1);
        __syncthreads();
        if (ch + 2 < NCH) prefetch(ch + 2, ch & 1);
        CP_COMMIT();
    }

    // ---- transposed epilogue: row m=(b,s), col k -> beta_t[b][k][s] ----
    #pragma unroll
    for (int nt = 0; nt < 4; nt++) {
        const int col = wn * 32 + nt * 8 + 2 * (lane & 3);
        #pragma unroll
        for (int mt = 0; mt < 4; mt++) {
            const int m0 = bm + wm * 64 + mt * 16 + (lane >> 2);
            float* d0 = g_beta + ((size_t)((m0 >> 12) * KK + col)) * SS + (m0 & (SS - 1));
            d0[0]  = acc[mt][nt][0];
            d0[SS] = acc[mt][nt][1];
            const int m1 = m0 + 8;
            float* d1 = g_beta + ((size_t)((m1 >> 12) * KK + col)) * SS + (m1 & (SS - 1));
            d1[0]  = acc[mt][nt][2];
            d1[SS] = acc[mt][nt][3];
        }
    }
}

// ============================================================================
// GEMM2 (fp16 m16n8k16): y = sr_seq @ W_out^T + b_out, fp32 accum.
// A = g_srseq_h (S,B,K) fp16, B = g_wout_h (D,K) fp16. KD=128, KC=64, NCH=2.
// smem rows padded to 144 B (36 u32); 72 KB total -> 2 CTAs/SM.
// ============================================================================
#define SPAD_U 36                 // u32 per smem row (72 halves, 144 B)
#define HSTG_U (128 * SPAD_U)     // u32 per tile stage

__global__ __launch_bounds__(256, 2)
void gemm_h(const __half* __restrict__ A, const __half* __restrict__ Bt,
            float* __restrict__ C, const float* __restrict__ bias, int ldc)
{
    constexpr int KD = 128;       // halves per row
    constexpr int KCH = 64;       // K per chunk
    constexpr int NCH = KD / KCH; // 2
    extern __shared__ uint32_t smu[];
    uint32_t* AsB = smu;                       // [2][128][36]
    uint32_t* BsB = smu + NSTG * HSTG_U;

    const int tid = threadIdx.x;
    const int bn = blockIdx.x * 128;
    const int bm = blockIdx.y * 128;
    const int lane = tid & 31;
    const int w = tid >> 5;
    const int wm = w >> 2;
    const int wn = w & 3;

    float acc[4][4][4];
    #pragma unroll
    for (int i = 0; i < 4; i++)
        #pragma unroll
        for (int j = 0; j < 4; j++)
            #pragma unroll
            for (int r = 0; r < 4; r++) acc[i][j][r] = 0.0f;

    const __half* Ag = A + (size_t)bm * KD;
    const __half* Bg = Bt + (size_t)bn * KD;

    // per chunk: 128 rows x 8 cp16 per matrix = 1024 each; 256 thr -> 4 iters
    auto prefetch = [&](int ch, int st) {
        uint32_t* as = AsB + st * HSTG_U;
        uint32_t* bs = BsB + st * HSTG_U;
        #pragma unroll
        for (int it = 0; it < 4; it++) {
            int idx = tid + it * 256;
            int r = idx >> 3, c4 = idx & 7;
            cp16(as + r * SPAD_U + c4 * 4, Ag + (size_t)r * KD + ch * KCH + c4 * 8);
            cp16(bs + r * SPAD_U + c4 * 4, Bg + (size_t)r * KD + ch * KCH + c4 * 8);
        }
    };

    auto compute = [&](int st) {
        const uint32_t* as = AsB + st * HSTG_U
                           + (wm * 64 + (lane >> 2)) * SPAD_U + (lane & 3);
        const uint32_t* bs = BsB + st * HSTG_U
                           + (wn * 32 + (lane >> 2)) * SPAD_U + (lane & 3);
        uint32_t a[2][4][4], b[2][4][2];
        auto load_frag = [&](int buf, int ks) {
            const int k = ks * 8;       // u32 offset = 16 halves per step
            #pragma unroll
            for (int mt = 0; mt < 4; mt++) {
                const uint32_t* p = as + mt * 16 * SPAD_U + k;
                a[buf][mt][0] = p[0];
                a[buf][mt][1] = p[8 * SPAD_U];
                a[buf][mt][2] = p[4];
                a[buf][mt][3] = p[8 * SPAD_U + 4];
            }
            #pragma unroll
            for (int nt = 0; nt < 4; nt++) {
                const uint32_t* p = bs + nt * 8 * SPAD_U + k;
                b[buf][nt][0] = p[0];
                b[buf][nt][1] = p[4];
            }
        };
        load_frag(0, 0);
        #pragma unroll
        for (int ks = 0; ks < KCH / 16; ks++) {     // 4 k16 steps
            const int cur = ks & 1;
            if (ks + 1 < KCH / 16) load_frag(cur ^ 1, ks + 1);
            #pragma unroll
            for (int mt = 0; mt < 4; mt++)
                #pragma unroll
                for (int nt = 0; nt < 4; nt++)
                    MMA_F16(acc[mt][nt], a[cur][mt], b[cur][nt]);
        }
    };

    prefetch(0, 0); CP_COMMIT();
    prefetch(1, 1); CP_COMMIT();
    for (int ch = 0; ch < NCH; ch++) {
        CP_WAIT1();
        __syncthreads();
        compute(ch & 1);
        __syncthreads();
        CP_COMMIT();
    }

    // ---- epilogue ----
    #pragma unroll
    for (int nt = 0; nt < 4; nt++) {
        const int col = bn + wn * 32 + nt * 8 + 2 * (lane & 3);
        const float2 bv = *(const float2*)(bias + col);
        #pragma unroll
        for (int mt = 0; mt < 4; mt++) {
            const int row = bm + wm * 64 + mt * 16 + (lane >> 2);
            float2 v0 = { acc[mt][nt][0] + bv.x, acc[mt][nt][1] + bv.y };
            float2 v1 = { acc[mt][nt][2] + bv.x, acc[mt][nt][3] + bv.y };
            *(float2*)(C + (size_t)row * ldc + col) = v0;
            *(float2*)(C + (size_t)(row + 8) * ldc + col) = v1;
        }
    }
}

// ============================================================================
// pre-convert kernels
// ============================================================================
__global__ __launch_bounds__(256)
void tf32_round(const float* __restrict__ src, float* __restrict__ dst, int n)
{
    int i = blockIdx.x * blockDim.x + threadIdx.x;
    if (i < n) dst[i] = __uint_as_float(f2tf(src[i]));
}
__global__ __launch_bounds__(256)
void f32_to_f16(const float* __restrict__ src, __half* __restrict__ dst, int n)
{
    int i = blockIdx.x * blockDim.x + threadIdx.x;
    if (i < n) dst[i] = __float2half(src[i]);
}

// ============================================================================
// Scan over beta_t (B,K,S): contiguous timeline per (b,k) -> float4 loads,
// MLP 16. CH=32 + 32-step warmup (decay <= 0.5 guard: error <= 0.5^32).
// Writes sr_seq as fp16 (S,B,K). scan_serial is the exact fallback.
// ============================================================================
#define SCAN_CH   32
#define SCAN_NCH  (SS / SCAN_CH)

__device__ __forceinline__ bool r_is_diag(const float* R, int k) {
    bool ok = true;
    for (int i = k; i < KK * KK; i += KK) {
        int r = i / KK, c = i - r * KK;
        if (r != c && R[i] != 0.0f) ok = false;
    }
    return ok;
}

__global__ __launch_bounds__(KK)
void scan_par(const float* __restrict__ alpha, const float* __restrict__ omega,
              const float* __restrict__ R,
              float* __restrict__ srf, float* __restrict__ sif)
{
    const int chunk = blockIdx.x, b = blockIdx.y, k = threadIdx.x;

    const bool diag = (__syncthreads_and(r_is_diag(R, k) ? 1 : 0) != 0);
    const float mag = 1.0f / (1.0f + expf(-alpha[k]));
    const float dk = R[k * KK + k];
    const bool dec_ok = (__syncthreads_and((mag * fabsf(dk)) <= 0.5f ? 1 : 0) != 0);
    if (!(diag && dec_ok)) return;

    const float cth = cosf(omega[k]);
    const float sth = sinf(omega[k]);
    const float Ac = dk * mag * cth;
    const float Bc = dk * mag * sth;

    const int t0 = chunk * SCAN_CH;
    const float* bt = g_beta + ((size_t)(b * KK + k)) * SS;

    float4 wv[8], mv[8];
    if (chunk > 0) {
        const float4* wp4 = (const float4*)(bt + t0 - SCAN_CH);
        #pragma unroll
        for (int i = 0; i < 8; i++) wv[i] = __ldg(wp4 + i);
    }
    const float4* mp4 = (const float4*)(bt + t0);
    #pragma unroll
    for (int i = 0; i < 8; i++) mv[i] = __ldg(mp4 + i);

    float sr = 0.0f, si = 0.0f;
    auto step = [&](float v) {
        float gb = dk * v;
        float nr = fmaf(Ac, sr, fmaf(-Bc, si, gb));
        float ni = fmaf(Bc, sr, Ac * si);
        sr = nr; si = ni;
    };

    if (chunk > 0) {
        #pragma unroll
        for (int g = 0; g < 8; g++) {
            step(wv[g].x); step(wv[g].y); step(wv[g].z); step(wv[g].w);
        }
    }

    __half* sp = g_srseq_h + ((size_t)t0 * BB + b) * KK + k;
    #pragma unroll
    for (int g = 0; g < 8; g++) {
        step(mv[g].x); sp[(size_t)(g * 4 + 0) * (BB * KK)] = __float2half(sr);
        step(mv[g].y); sp[(size_t)(g * 4 + 1) * (BB * KK)] = __float2half(sr);
        step(mv[g].z); sp[(size_t)(g * 4 + 2) * (BB * KK)] = __float2half(sr);
        step(mv[g].w); sp[(size_t)(g * 4 + 3) * (BB * KK)] = __float2half(sr);
    }

    if (chunk == SCAN_NCH - 1) { srf[b * KK + k] = sr; sif[b * KK + k] = si; }
}

__global__ __launch_bounds__(KK)
void scan_serial(const float* __restrict__ alpha, const float* __restrict__ omega,
                 const float* __restrict__ R,
                 float* __restrict__ srf, float* __restrict__ sif)
{
    const int b = blockIdx.x, k = threadIdx.x;

    const bool diag = (__syncthreads_and(r_is_diag(R, k) ? 1 : 0) != 0);
    const float mag = 1.0f / (1.0f + expf(-alpha[k]));
    const float dk = R[k * KK + k];
    const bool dec_ok = (__syncthreads_and((mag * fabsf(dk)) <= 0.5f ? 1 : 0) != 0);
    if (diag && dec_ok) return;   // parallel kernel handled it

    const float cth = cosf(omega[k]);
    const float sth = sinf(omega[k]);

    const float* bt = g_beta + ((size_t)(b * KK + k)) * SS;   // contiguous in t
    __half* sp = g_srseq_h + (size_t)b * KK + k;
    float sr = 0.0f, si = 0.0f;

    if (diag) {
        const float Ac = dk * mag * cth;
        const float Bc = dk * mag * sth;
        #pragma unroll 4
        for (int t = 0; t < SS; t++) {
            float gb = dk * __ldg(bt + t);
            float nr = fmaf(Ac, sr, fmaf(-Bc, si, gb));
            float ni = fmaf(Bc, sr, Ac * si);
            sr = nr; si = ni;
            sp[(size_t)t * (BB * KK)] = __float2half(sr);
        }
    } else {
        __shared__ float nrs[KK], nis[KK];
        for (int t = 0; t < SS; t++) {
            float btv = __ldg(bt + t);
            float nr = fmaf(mag * cth, sr, fmaf(-mag * sth, si, btv));
            float ni = mag * fmaf(sr, sth, si * cth);
            nrs[k] = nr; nis[k] = ni;
            __syncthreads();
            float a0 = 0.0f, a1 = 0.0f;
            #pragma unroll 8
            for (int j = 0; j < KK; j++) {
                float rj = R[j * KK + k];
                a0 = fmaf(nrs[j], rj, a0);
                a1 = fmaf(nis[j], rj, a1);
            }
            __syncthreads();
            sr = a0; si = a1;
            sp[(size_t)t * (BB * KK)] = __float2half(sr);
        }
    }
    srf[b * KK + k] = sr;
    sif[b * KK + k] = si;
}

// ============================================================================
// LayerNorm + transpose, warp-per-row: row r = s*B + b of g_y -> out[b][s][:]
// ============================================================================
__global__ __launch_bounds__(256)
void ln_kernel(const float* __restrict__ g, const float* __restrict__ bb,
               float* __restrict__ out)
{
    const int r = blockIdx.x * 8 + (threadIdx.x >> 5);
    const int lane = threadIdx.x & 31;

    const float4* yp = (const float4*)(g_y + (size_t)r * DD);

    float4 v[8];
    #pragma unroll
    for (int i = 0; i < 8; i++) v[i] = yp[lane + i * 32];

    float sum = 0.0f, sq = 0.0f;
    #pragma unroll
    for (int i = 0; i < 8; i++) {
        sum += (v[i].x + v[i].y) + (v[i].z + v[i].w);
        sq = fmaf(v[i].x, v[i].x, sq);
        sq = fmaf(v[i].y, v[i].y, sq);
        sq = fmaf(v[i].z, v[i].z, sq);
        sq = fmaf(v[i].w, v[i].w, sq);
    }
    #pragma unroll
    for (int o = 16; o > 0; o >>= 1) {
        sum += __shfl_xor_sync(0xffffffffu, sum, o);
        sq  += __shfl_xor_sync(0xffffffffu, sq,  o);
    }

    const float mu  = sum * (1.0f / DD);
    const float var = sq * (1.0f / DD) - mu * mu;
    const float inv = rsqrtf(var + LN_EPS);

    const int s = r >> 3;
    const int b = r & 7;
    float4* op = (float4*)(out + ((size_t)b * SS + s) * DD);

    #pragma unroll
    for (int i = 0; i < 8; i++) {
        const float4 gg = ((const float4*)g)[lane + i * 32];
        const float4 b4 = ((const float4*)bb)[lane + i * 32];
        float4 o;
        o.x = fmaf((v[i].x - mu) * inv, gg.x, b4.x);
        o.y = fmaf((v[i].y - mu) * inv, gg.y, b4.y);
        o.z = fmaf((v[i].z - mu) * inv, gg.z, b4.z);
        o.w = fmaf((v[i].w - mu) * inv, gg.w, b4.w);
        op[lane + i * 32] = o;
    }
}

// ============================================================================
// launch
// ============================================================================
extern "C" void kernel_launch(void* const* d_in, const int* in_sizes, int n_in,
                              void* d_out, int out_size)
{
    const float* x     = (const float*)d_in[0];
    const float* alpha = (const float*)d_in[1];
    const float* omega = (const float*)d_in[2];
    const float* W_in  = (const float*)d_in[3];
    const float* R     = (const float*)d_in[4];
    const float* W_out = (const float*)d_in[5];
    const float* b_out = (const float*)d_in[6];
    const float* ln_g  = (const float*)d_in[7];
    const float* ln_b  = (const float*)d_in[8];

    float* out = (float*)d_out;                   // (B,S,D)
    float* srf = out + (size_t)BB * SS * DD;      // (B,K)
    float* sif = srf + (size_t)BB * KK;           // (B,K)

    float*  y_p;     cudaGetSymbolAddress((void**)&y_p,     g_y);
    float*  win_p;   cudaGetSymbolAddress((void**)&win_p,   g_win_tf);
    __half* wouth_p; cudaGetSymbolAddress((void**)&wouth_p, g_wout_h);
    __half* srh_p;   cudaGetSymbolAddress((void**)&srh_p,   g_srseq_h);

    const int SMEM = 2 * NSTG * STG_F * (int)sizeof(float);   // 73728 B (both gemms)
    cudaFuncSetAttribute(gemm_beta, cudaFuncAttributeMaxDynamicSharedMemorySize, SMEM);
    cudaFuncSetAttribute(gemm_h,    cudaFuncAttributeMaxDynamicSharedMemorySize, SMEM);
    cudaFuncSetAttribute(gemm_beta, cudaFuncAttributePreferredSharedMemoryCarveout, 100);
    cudaFuncSetAttribute(gemm_h,    cudaFuncAttributePreferredSharedMemoryCarveout, 100);

    // 0) pre-convert weights
    tf32_round<<<(KK * DD + 255) / 256, 256>>>(W_in, win_p, KK * DD);
    f32_to_f16<<<(DD * KK + 255) / 256, 256>>>(W_out, wouth_p, DD * KK);

    // 1) beta^T = (x @ W_in^T)^T -> g_beta (B,K,S)
    gemm_beta<<<dim3(1, MM / 128), 256, SMEM>>>(x, win_p);

    // 2) scan (parallel fast path + exact fallback) -> g_srseq_h fp16
    scan_par<<<dim3(SCAN_NCH, BB), KK>>>(alpha, omega, R, srf, sif);
    scan_serial<<<BB, KK>>>(alpha, omega, R, srf, sif);

    // 3) y = sr_seq @ W_out^T + b_out  (fp16 MMA, fp32 accum)
    gemm_h<<<dim3(DD / 128, MM / 128), 256, SMEM>>>(srh_p, wouth_p, y_p, b_out, DD);

    // 4) LayerNorm + transpose to (B,S,D)
    ln_kernel<<<MM / 8, 256>>>(ln_g, ln_b, out);
}

// round 11
// speedup vs baseline: 1.1821x; 1.1026x over previous
#include <cuda_runtime.h>
#include <cuda_fp16.h>
#include <cstdint>

#define BB   8
#define SS   4096
#define DD   1024
#define KK   128
#define MM   (BB * SS)
#define LN_EPS 1e-5f

// ---------------- scratch (static device arrays; no allocations) ----------------
__device__ float  g_beta   [ (size_t)MM * KK ];  // beta TRANSPOSED: (B,K,S) 16 MB
__device__ __half g_srseq_h[ (size_t)MM * KK ];  // (S,B,K) fp16, 8 MB
__device__ __half g_y_h    [ (size_t)MM * DD ];  // (S*B, D) fp16, 64 MB
__device__ float  g_win_tf [ (size_t)KK * DD ];  // W_in  tf32-rounded
__device__ __half g_wout_h [ (size_t)DD * KK ];  // W_out fp16

// ============================ helpers ============================
__device__ __forceinline__ uint32_t smem_u32(const void* p) {
    uint32_t a;
    asm("{ .reg .u64 t; cvta.to.shared.u64 t, %1; cvt.u32.u64 %0, t; }" : "=r"(a) : "l"(p));
    return a;
}
__device__ __forceinline__ uint32_t f2tf(float f) {
    uint32_t u;
    asm("cvt.rna.tf32.f32 %0, %1;" : "=r"(u) : "f"(f));
    return u;
}
__device__ __forceinline__ void cp16(void* dst, const void* src) {
    uint32_t d = smem_u32(dst);
    asm volatile("cp.async.cg.shared.global [%0], [%1], 16;" :: "r"(d), "l"(src));
}
#define CP_COMMIT() asm volatile("cp.async.commit_group;" ::: "memory")
#define CP_WAIT1()  asm volatile("cp.async.wait_group 1;"  ::: "memory")

#define MMA_TF32(c, a, b) \
    asm volatile("mma.sync.aligned.m16n8k8.row.col.f32.tf32.tf32.f32 " \
        "{%0,%1,%2,%3}, {%4,%5,%6,%7}, {%8,%9}, {%0,%1,%2,%3};" \
        : "+f"((c)[0]), "+f"((c)[1]), "+f"((c)[2]), "+f"((c)[3]) \
        : "r"((a)[0]), "r"((a)[1]), "r"((a)[2]), "r"((a)[3]), \
          "r"((b)[0]), "r"((b)[1]))

#define MMA_F16(c, a, b) \
    asm volatile("mma.sync.aligned.m16n8k16.row.col.f32.f16.f16.f32 " \
        "{%0,%1,%2,%3}, {%4,%5,%6,%7}, {%8,%9}, {%0,%1,%2,%3};" \
        : "+f"((c)[0]), "+f"((c)[1]), "+f"((c)[2]), "+f"((c)[3]) \
        : "r"((a)[0]), "r"((a)[1]), "r"((a)[2]), "r"((a)[3]), \
          "r"((b)[0]), "r"((b)[1]))

// ============================================================================
// GEMM1 (tf32): beta^T = (x @ W_in^T)^T, written as beta_t (B,K,S).
// ============================================================================
#define KC   32
#define SPAD 36
#define STG_F (128 * SPAD)
#define NSTG 2

__global__ __launch_bounds__(256, 2)
void gemm_beta(const float* __restrict__ A, const float* __restrict__ Bt)
{
    constexpr int KD = 1024;
    constexpr int NCH = KD / KC;
    extern __shared__ float sm[];
    float* AsB = sm;
    float* BsB = sm + NSTG * STG_F;

    const int tid = threadIdx.x;
    const int bm = blockIdx.y * 128;
    const int lane = tid & 31;
    const int w = tid >> 5;
    const int wm = w >> 2;
    const int wn = w & 3;

    float acc[4][4][4];
    #pragma unroll
    for (int i = 0; i < 4; i++)
        #pragma unroll
        for (int j = 0; j < 4; j++)
            #pragma unroll
            for (int r = 0; r < 4; r++) acc[i][j][r] = 0.0f;

    const float* Ag = A + (size_t)bm * KD;
    const float* Bg = Bt;

    auto prefetch = [&](int ch, int st) {
        float* as = AsB + st * STG_F;
        float* bs = BsB + st * STG_F;
        #pragma unroll
        for (int it = 0; it < 4; it++) {
            int idx = tid + it * 256;
            int r = idx >> 3, c4 = idx & 7;
            cp16(as + r * SPAD + c4 * 4, Ag + (size_t)r * KD + ch * KC + c4 * 4);
            cp16(bs + r * SPAD + c4 * 4, Bg + (size_t)r * KD + ch * KC + c4 * 4);
        }
    };

    auto compute = [&](int st) {
        const uint32_t* as = (const uint32_t*)(AsB + st * STG_F)
                           + (wm * 64 + (lane >> 2)) * SPAD + (lane & 3);
        const uint32_t* bs = (const uint32_t*)(BsB + st * STG_F)
                           + (wn * 32 + (lane >> 2)) * SPAD + (lane & 3);
        uint32_t a[2][4][4], b[2][4][2];
        auto load_frag = [&](int buf, int ks) {
            const int k = ks * 8;
            #pragma unroll
            for (int mt = 0; mt < 4; mt++) {
                const uint32_t* p = as + mt * 16 * SPAD + k;
                a[buf][mt][0] = p[0];
                a[buf][mt][1] = p[8 * SPAD];
                a[buf][mt][2] = p[4];
                a[buf][mt][3] = p[8 * SPAD + 4];
            }
            #pragma unroll
            for (int nt = 0; nt < 4; nt++) {
                const uint32_t* p = bs + nt * 8 * SPAD + k;
                b[buf][nt][0] = p[0];
                b[buf][nt][1] = p[4];
            }
        };
        load_frag(0, 0);
        #pragma unroll
        for (int ks = 0; ks < KC / 8; ks++) {
            const int cur = ks & 1;
            if (ks + 1 < KC / 8) load_frag(cur ^ 1, ks + 1);
            #pragma unroll
            for (int mt = 0; mt < 4; mt++)
                #pragma unroll
                for (int nt = 0; nt < 4; nt++)
                    MMA_TF32(acc[mt][nt], a[cur][mt], b[cur][nt]);
        }
    };

    prefetch(0, 0); CP_COMMIT();
    prefetch(1, 1); CP_COMMIT();
    for (int ch = 0; ch < NCH; ch++) {
        CP_WAIT1();
        __syncthreads();
        compute(ch & 1);
        __syncthreads();
        if (ch + 2 < NCH) prefetch(ch + 2, ch & 1);
        CP_COMMIT();
    }

    // ---- transposed epilogue: row m=(b,s), col k -> beta_t[b][k][s] ----
    #pragma unroll
    for (int nt = 0; nt < 4; nt++) {
        const int col = wn * 32 + nt * 8 + 2 * (lane & 3);
        #pragma unroll
        for (int mt = 0; mt < 4; mt++) {
            const int m0 = bm + wm * 64 + mt * 16 + (lane >> 2);
            float* d0 = g_beta + ((size_t)((m0 >> 12) * KK + col)) * SS + (m0 & (SS - 1));
            d0[0]  = acc[mt][nt][0];
            d0[SS] = acc[mt][nt][1];
            const int m1 = m0 + 8;
            float* d1 = g_beta + ((size_t)((m1 >> 12) * KK + col)) * SS + (m1 & (SS - 1));
            d1[0]  = acc[mt][nt][2];
            d1[SS] = acc[mt][nt][3];
        }
    }
}

// ============================================================================
// GEMM2 (fp16 m16n8k16): y_h = fp16( sr_seq @ W_out^T + b_out ), fp32 accum.
// ============================================================================
#define SPAD_U 36
#define HSTG_U (128 * SPAD_U)

__global__ __launch_bounds__(256, 2)
void gemm_h(const __half* __restrict__ A, const __half* __restrict__ Bt,
            __half* __restrict__ C, const float* __restrict__ bias, int ldc)
{
    constexpr int KD = 128;
    constexpr int KCH = 64;
    constexpr int NCH = KD / KCH;
    extern __shared__ uint32_t smu[];
    uint32_t* AsB = smu;
    uint32_t* BsB = smu + NSTG * HSTG_U;

    const int tid = threadIdx.x;
    const int bn = blockIdx.x * 128;
    const int bm = blockIdx.y * 128;
    const int lane = tid & 31;
    const int w = tid >> 5;
    const int wm = w >> 2;
    const int wn = w & 3;

    float acc[4][4][4];
    #pragma unroll
    for (int i = 0; i < 4; i++)
        #pragma unroll
        for (int j = 0; j < 4; j++)
            #pragma unroll
            for (int r = 0; r < 4; r++) acc[i][j][r] = 0.0f;

    const __half* Ag = A + (size_t)bm * KD;
    const __half* Bg = Bt + (size_t)bn * KD;

    auto prefetch = [&](int ch, int st) {
        uint32_t* as = AsB + st * HSTG_U;
        uint32_t* bs = BsB + st * HSTG_U;
        #pragma unroll
        for (int it = 0; it < 4; it++) {
            int idx = tid + it * 256;
            int r = idx >> 3, c4 = idx & 7;
            cp16(as + r * SPAD_U + c4 * 4, Ag + (size_t)r * KD + ch * KCH + c4 * 8);
            cp16(bs + r * SPAD_U + c4 * 4, Bg + (size_t)r * KD + ch * KCH + c4 * 8);
        }
    };

    auto compute = [&](int st) {
        const uint32_t* as = AsB + st * HSTG_U
                           + (wm * 64 + (lane >> 2)) * SPAD_U + (lane & 3);
        const uint32_t* bs = BsB + st * HSTG_U
                           + (wn * 32 + (lane >> 2)) * SPAD_U + (lane & 3);
        uint32_t a[2][4][4], b[2][4][2];
        auto load_frag = [&](int buf, int ks) {
            const int k = ks * 8;
            #pragma unroll
            for (int mt = 0; mt < 4; mt++) {
                const uint32_t* p = as + mt * 16 * SPAD_U + k;
                a[buf][mt][0] = p[0];
                a[buf][mt][1] = p[8 * SPAD_U];
                a[buf][mt][2] = p[4];
                a[buf][mt][3] = p[8 * SPAD_U + 4];
            }
            #pragma unroll
            for (int nt = 0; nt < 4; nt++) {
                const uint32_t* p = bs + nt * 8 * SPAD_U + k;
                b[buf][nt][0] = p[0];
                b[buf][nt][1] = p[4];
            }
        };
        load_frag(0, 0);
        #pragma unroll
        for (int ks = 0; ks < KCH / 16; ks++) {
            const int cur = ks & 1;
            if (ks + 1 < KCH / 16) load_frag(cur ^ 1, ks + 1);
            #pragma unroll
            for (int mt = 0; mt < 4; mt++)
                #pragma unroll
                for (int nt = 0; nt < 4; nt++)
                    MMA_F16(acc[mt][nt], a[cur][mt], b[cur][nt]);
        }
    };

    prefetch(0, 0); CP_COMMIT();
    prefetch(1, 1); CP_COMMIT();
    for (int ch = 0; ch < NCH; ch++) {
        CP_WAIT1();
        __syncthreads();
        compute(ch & 1);
        __syncthreads();
        CP_COMMIT();
    }

    // ---- epilogue: fp16 y ----
    #pragma unroll
    for (int nt = 0; nt < 4; nt++) {
        const int col = bn + wn * 32 + nt * 8 + 2 * (lane & 3);
        const float2 bv = *(const float2*)(bias + col);
        #pragma unroll
        for (int mt = 0; mt < 4; mt++) {
            const int row = bm + wm * 64 + mt * 16 + (lane >> 2);
            __half2 h0 = __floats2half2_rn(acc[mt][nt][0] + bv.x, acc[mt][nt][1] + bv.y);
            __half2 h1 = __floats2half2_rn(acc[mt][nt][2] + bv.x, acc[mt][nt][3] + bv.y);
            *(__half2*)(C + (size_t)row * ldc + col) = h0;
            *(__half2*)(C + (size_t)(row + 8) * ldc + col) = h1;
        }
    }
}

// ============================================================================
// pre-convert kernels
// ============================================================================
__global__ __launch_bounds__(256)
void tf32_round(const float* __restrict__ src, float* __restrict__ dst, int n)
{
    int i = blockIdx.x * blockDim.x + threadIdx.x;
    if (i < n) dst[i] = __uint_as_float(f2tf(src[i]));
}
__global__ __launch_bounds__(256)
void f32_to_f16(const float* __restrict__ src, __half* __restrict__ dst, int n)
{
    int i = blockIdx.x * blockDim.x + threadIdx.x;
    if (i < n) dst[i] = __float2half(src[i]);
}

// ============================================================================
// Scan over beta_t (B,K,S). CH=16 (2048 blocks) + 32-step warmup
// (decay <= 0.5 guard: truncation error <= 0.5^32). Contiguous float4 loads.
// Writes sr_seq fp16 (S,B,K). scan_serial is the exact fallback.
// ============================================================================
#define SCAN_CH   16
#define SCAN_NCH  (SS / SCAN_CH)
#define SCAN_WARM 32

__device__ __forceinline__ bool r_is_diag(const float* R, int k) {
    bool ok = true;
    for (int i = k; i < KK * KK; i += KK) {
        int r = i / KK, c = i - r * KK;
        if (r != c && R[i] != 0.0f) ok = false;
    }
    return ok;
}

__global__ __launch_bounds__(KK)
void scan_par(const float* __restrict__ alpha, const float* __restrict__ omega,
              const float* __restrict__ R,
              float* __restrict__ srf, float* __restrict__ sif)
{
    const int chunk = blockIdx.x, b = blockIdx.y, k = threadIdx.x;

    const bool diag = (__syncthreads_and(r_is_diag(R, k) ? 1 : 0) != 0);
    const float mag = 1.0f / (1.0f + expf(-alpha[k]));
    const float dk = R[k * KK + k];
    const bool dec_ok = (__syncthreads_and((mag * fabsf(dk)) <= 0.5f ? 1 : 0) != 0);
    if (!(diag && dec_ok)) return;

    const float cth = cosf(omega[k]);
    const float sth = sinf(omega[k]);
    const float Ac = dk * mag * cth;
    const float Bc = dk * mag * sth;

    const int t0 = chunk * SCAN_CH;
    const int warm = (t0 >= SCAN_WARM) ? SCAN_WARM : t0;   // t0 multiple of 16
    const float* bt = g_beta + ((size_t)(b * KK + k)) * SS + (t0 - warm);

    float sr = 0.0f, si = 0.0f;
    auto step = [&](float v) {
        float gb = dk * v;
        float nr = fmaf(Ac, sr, fmaf(-Bc, si, gb));
        float ni = fmaf(Bc, sr, Ac * si);
        sr = nr; si = ni;
    };

    // warmup (0, 16, or 32 steps; all loads contiguous, issued per 4-float4 batch)
    const float4* p4 = (const float4*)bt;
    for (int h = 0; h < warm / 16; h++) {
        float4 wv[4];
        #pragma unroll
        for (int i = 0; i < 4; i++) wv[i] = __ldg(p4 + i);
        p4 += 4;
        #pragma unroll
        for (int i = 0; i < 4; i++) {
            step(wv[i].x); step(wv[i].y); step(wv[i].z); step(wv[i].w);
        }
    }

    // main: 16 steps (4 float4)
    float4 mv[4];
    #pragma unroll
    for (int i = 0; i < 4; i++) mv[i] = __ldg(p4 + i);

    __half* sp = g_srseq_h + ((size_t)t0 * BB + b) * KK + k;
    #pragma unroll
    for (int g = 0; g < 4; g++) {
        step(mv[g].x); sp[(size_t)(g * 4 + 0) * (BB * KK)] = __float2half(sr);
        step(mv[g].y); sp[(size_t)(g * 4 + 1) * (BB * KK)] = __float2half(sr);
        step(mv[g].z); sp[(size_t)(g * 4 + 2) * (BB * KK)] = __float2half(sr);
        step(mv[g].w); sp[(size_t)(g * 4 + 3) * (BB * KK)] = __float2half(sr);
    }

    if (chunk == SCAN_NCH - 1) { srf[b * KK + k] = sr; sif[b * KK + k] = si; }
}

__global__ __launch_bounds__(KK)
void scan_serial(const float* __restrict__ alpha, const float* __restrict__ omega,
                 const float* __restrict__ R,
                 float* __restrict__ srf, float* __restrict__ sif)
{
    const int b = blockIdx.x, k = threadIdx.x;

    const bool diag = (__syncthreads_and(r_is_diag(R, k) ? 1 : 0) != 0);
    const float mag = 1.0f / (1.0f + expf(-alpha[k]));
    const float dk = R[k * KK + k];
    const bool dec_ok = (__syncthreads_and((mag * fabsf(dk)) <= 0.5f ? 1 : 0) != 0);
    if (diag && dec_ok) return;   // parallel kernel handled it

    const float cth = cosf(omega[k]);
    const float sth = sinf(omega[k]);

    const float* bt = g_beta + ((size_t)(b * KK + k)) * SS;
    __half* sp = g_srseq_h + (size_t)b * KK + k;
    float sr = 0.0f, si = 0.0f;

    if (diag) {
        const float Ac = dk * mag * cth;
        const float Bc = dk * mag * sth;
        #pragma unroll 4
        for (int t = 0; t < SS; t++) {
            float gb = dk * __ldg(bt + t);
            float nr = fmaf(Ac, sr, fmaf(-Bc, si, gb));
            float ni = fmaf(Bc, sr, Ac * si);
            sr = nr; si = ni;
            sp[(size_t)t * (BB * KK)] = __float2half(sr);
        }
    } else {
        __shared__ float nrs[KK], nis[KK];
        for (int t = 0; t < SS; t++) {
            float btv = __ldg(bt + t);
            float nr = fmaf(mag * cth, sr, fmaf(-mag * sth, si, btv));
            float ni = mag * fmaf(sr, sth, si * cth);
            nrs[k] = nr; nis[k] = ni;
            __syncthreads();
            float a0 = 0.0f, a1 = 0.0f;
            #pragma unroll 8
            for (int j = 0; j < KK; j++) {
                float rj = R[j * KK + k];
                a0 = fmaf(nrs[j], rj, a0);
                a1 = fmaf(nis[j], rj, a1);
            }
            __syncthreads();
            sr = a0; si = a1;
            sp[(size_t)t * (BB * KK)] = __float2half(sr);
        }
    }
    srf[b * KK + k] = sr;
    sif[b * KK + k] = si;
}

// ============================================================================
// LayerNorm + transpose over fp16 y: row r = s*B + b -> out[b][s][:] (fp32)
// warp-per-row; lane loads 4 x float4 (= 32 halves).
// ============================================================================
__global__ __launch_bounds__(256)
void ln_kernel(const float* __restrict__ g, const float* __restrict__ bb,
               float* __restrict__ out)
{
    const int r = blockIdx.x * 8 + (threadIdx.x >> 5);
    const int lane = threadIdx.x & 31;

    const uint4* yp = (const uint4*)(g_y_h + (size_t)r * DD);   // 128 uint4/row

    float vals[32];
    float sum = 0.0f, sq = 0.0f;
    #pragma unroll
    for (int j = 0; j < 4; j++) {
        uint4 u = __ldg(yp + lane + j * 32);
        float2 f0 = __half22float2(*(__half2*)&u.x);
        float2 f1 = __half22float2(*(__half2*)&u.y);
        float2 f2 = __half22float2(*(__half2*)&u.z);
        float2 f3 = __half22float2(*(__half2*)&u.w);
        vals[j*8+0] = f0.x; vals[j*8+1] = f0.y;
        vals[j*8+2] = f1.x; vals[j*8+3] = f1.y;
        vals[j*8+4] = f2.x; vals[j*8+5] = f2.y;
        vals[j*8+6] = f3.x; vals[j*8+7] = f3.y;
        #pragma unroll
        for (int c = 0; c < 8; c++) {
            sum += vals[j*8+c];
            sq = fmaf(vals[j*8+c], vals[j*8+c], sq);
        }
    }
    #pragma unroll
    for (int o = 16; o > 0; o >>= 1) {
        sum += __shfl_xor_sync(0xffffffffu, sum, o);
        sq  += __shfl_xor_sync(0xffffffffu, sq,  o);
    }

    const float mu  = sum * (1.0f / DD);
    const float var = sq * (1.0f / DD) - mu * mu;
    const float inv = rsqrtf(var + LN_EPS);

    const int s = r >> 3;            // r = s*B + b, B=8
    const int b = r & 7;
    float4* op = (float4*)(out + ((size_t)b * SS + s) * DD);

    #pragma unroll
    for (int j = 0; j < 4; j++) {
        #pragma unroll
        for (int h = 0; h < 2; h++) {
            const int fi = 2 * (lane + j * 32) + h;     // float4 index in row
            const float4 gg = __ldg((const float4*)g + fi);
            const float4 b4 = __ldg((const float4*)bb + fi);
            float4 o;
            o.x = fmaf((vals[j*8+h*4+0] - mu) * inv, gg.x, b4.x);
            o.y = fmaf((vals[j*8+h*4+1] - mu) * inv, gg.y, b4.y);
            o.z = fmaf((vals[j*8+h*4+2] - mu) * inv, gg.z, b4.z);
            o.w = fmaf((vals[j*8+h*4+3] - mu) * inv, gg.w, b4.w);
            op[fi] = o;
        }
    }
}

// ============================================================================
// launch
// ============================================================================
extern "C" void kernel_launch(void* const* d_in, const int* in_sizes, int n_in,
                              void* d_out, int out_size)
{
    const float* x     = (const float*)d_in[0];
    const float* alpha = (const float*)d_in[1];
    const float* omega = (const float*)d_in[2];
    const float* W_in  = (const float*)d_in[3];
    const float* R     = (const float*)d_in[4];
    const float* W_out = (const float*)d_in[5];
    const float* b_out = (const float*)d_in[6];
    const float* ln_g  = (const float*)d_in[7];
    const float* ln_b  = (const float*)d_in[8];

    float* out = (float*)d_out;                   // (B,S,D)
    float* srf = out + (size_t)BB * SS * DD;      // (B,K)
    float* sif = srf + (size_t)BB * KK;           // (B,K)

    float*  win_p;   cudaGetSymbolAddress((void**)&win_p,   g_win_tf);
    __half* wouth_p; cudaGetSymbolAddress((void**)&wouth_p, g_wout_h);
    __half* srh_p;   cudaGetSymbolAddress((void**)&srh_p,   g_srseq_h);
    __half* yh_p;    cudaGetSymbolAddress((void**)&yh_p,    g_y_h);

    const int SMEM = 2 * NSTG * STG_F * (int)sizeof(float);   // 73728 B
    cudaFuncSetAttribute(gemm_beta, cudaFuncAttributeMaxDynamicSharedMemorySize, SMEM);
    cudaFuncSetAttribute(gemm_h,    cudaFuncAttributeMaxDynamicSharedMemorySize, SMEM);
    cudaFuncSetAttribute(gemm_beta, cudaFuncAttributePreferredSharedMemoryCarveout, 100);
    cudaFuncSetAttribute(gemm_h,    cudaFuncAttributePreferredSharedMemoryCarveout, 100);

    // 0) pre-convert weights
    tf32_round<<<(KK * DD + 255) / 256, 256>>>(W_in, win_p, KK * DD);
    f32_to_f16<<<(DD * KK + 255) / 256, 256>>>(W_out, wouth_p, DD * KK);

    // 1) beta^T = (x @ W_in^T)^T -> g_beta (B,K,S)
    gemm_beta<<<dim3(1, MM / 128), 256, SMEM>>>(x, win_p);

    // 2) scan (parallel fast path + exact fallback) -> g_srseq_h fp16
    scan_par<<<dim3(SCAN_NCH, BB), KK>>>(alpha, omega, R, srf, sif);
    scan_serial<<<BB, KK>>>(alpha, omega, R, srf, sif);

    // 3) y_h = fp16( sr_seq @ W_out^T + b_out )
    gemm_h<<<dim3(DD / 128, MM / 128), 256, SMEM>>>(srh_p, wouth_p, yh_p, b_out, DD);

    // 4) LayerNorm over fp16 y + transpose to (B,S,D) fp32
    ln_kernel<<<MM / 8, 256>>>(ln_g, ln_b, out);
}